// round 2
// baseline (speedup 1.0000x reference)
#include <cuda_runtime.h>

#define Bq 128
#define Nn 64
#define Dd 64
#define Aa 12
#define Hh 128
#define Ee 4032
#define NITERS 8

// -------- device scratch (no allocations allowed) --------
__device__ float g_edge_vals[74317824];   // B*E*A*A = 128*4032*144  (~297MB)
__device__ float g_X1[Bq*Nn*Hh];          // obs @ W1e[:D]
__device__ float g_X2[Bq*Nn*Hh];          // obs @ W1e[D:]
__device__ float g_node_vals[Bq*Nn*Aa];
__device__ float g_q[Bq*Nn*Aa];
__device__ __align__(16) float g_msg_forw[Bq*Ee*Aa];    // 6,193,152
__device__ __align__(16) float g_msg_back[Bq*Ee*Aa];
__device__ int   g_a[Bq*Nn];
__device__ float g_qmax[Bq];

// ---------------------------------------------------------
// K0: node MLP + per-node halves of edge layer-1 (X1, X2)
// 8 rows per block, 128 threads (one per hidden unit).
// ---------------------------------------------------------
__global__ void k_node(const float* __restrict__ obs, const float* __restrict__ W1n,
                       const float* __restrict__ b1n, const float* __restrict__ W2n,
                       const float* __restrict__ b2n, const float* __restrict__ W1e) {
    int row0 = blockIdx.x * 8;         // row = b*N + n
    int t = threadIdx.x;               // 0..127
    __shared__ float so[8][64];
    __shared__ float sh[8][128];
    for (int i = t; i < 512; i += 128) so[i >> 6][i & 63] = obs[row0 * 64 + i];
    __syncthreads();
    for (int r = 0; r < 8; r++) {
        float s1 = b1n[t], x1 = 0.f, x2 = 0.f;
#pragma unroll 8
        for (int d = 0; d < 64; d++) {
            float o = so[r][d];
            s1 = fmaf(o, W1n[d * 128 + t], s1);
            x1 = fmaf(o, W1e[d * 128 + t], x1);
            x2 = fmaf(o, W1e[(64 + d) * 128 + t], x2);
        }
        sh[r][t] = fmaxf(s1, 0.f);
        g_X1[(row0 + r) * 128 + t] = x1;
        g_X2[(row0 + r) * 128 + t] = x2;
    }
    __syncthreads();
    if (t < 96) {
        int r = t / 12, a = t - r * 12;
        float nv = b2n[a];
#pragma unroll 8
        for (int k = 0; k < 128; k++) nv = fmaf(sh[r][k], W2n[k * 12 + a], nv);
        g_node_vals[(row0 + r) * 12 + a] = nv;
    }
}

// ---------------------------------------------------------
// K1: edge layer-2 GEMM. One block = 64 edges x 144 cols.
// W2e (128x144) + relu'd hidden tile (64x128, padded to 132) in SMEM.
// 256 threads, each computes 4 rows x 9 cols.
// ---------------------------------------------------------
__global__ void k_edge_gemm(const int* __restrict__ ef, const int* __restrict__ et,
                            const float* __restrict__ b1e, const float* __restrict__ W2e,
                            const float* __restrict__ b2e) {
    extern __shared__ float sm[];
    float* Wsh = sm;                    // 128*144 = 18432 floats
    float* hsh = sm + 18432;            // 64*132  =  8448 floats
    __shared__ int sf[64], st2[64];
    int b = blockIdx.y;
    int e0 = blockIdx.x * 64;
    int tid = threadIdx.x;

    if (tid < 64) { sf[tid] = ef[e0 + tid]; st2[tid] = et[e0 + tid]; }
    for (int i = tid; i < 128 * 144; i += 256) Wsh[i] = W2e[i];
    __syncthreads();

#pragma unroll 4
    for (int s = 0; s < 32; s++) {
        int idx = s * 256 + tid;
        int el = idx >> 7, k = idx & 127;
        float v = g_X1[(b * Nn + sf[el]) * Hh + k] + g_X2[(b * Nn + st2[el]) * Hh + k] + b1e[k];
        hsh[el * 132 + k] = fmaxf(v, 0.f);
    }
    __syncthreads();

    int tx = tid & 15, ty = tid >> 4;   // ty: 16 row-groups of 4, tx: 16 col lanes x 9 groups
    float acc[4][9];
#pragma unroll
    for (int r = 0; r < 4; r++)
#pragma unroll
        for (int j = 0; j < 9; j++) acc[r][j] = 0.f;

#pragma unroll 8
    for (int k = 0; k < 128; k++) {
        float hv[4], wv[9];
#pragma unroll
        for (int r = 0; r < 4; r++) hv[r] = hsh[(ty * 4 + r) * 132 + k];
#pragma unroll
        for (int j = 0; j < 9; j++) wv[j] = Wsh[k * 144 + tx + 16 * j];
#pragma unroll
        for (int r = 0; r < 4; r++)
#pragma unroll
            for (int j = 0; j < 9; j++) acc[r][j] = fmaf(hv[r], wv[j], acc[r][j]);
    }

    size_t base = ((size_t)b * Ee + e0) * 144;
#pragma unroll
    for (int r = 0; r < 4; r++) {
        int row = ty * 4 + r;
#pragma unroll
        for (int j = 0; j < 9; j++) {
            int col = tx + 16 * j;
            g_edge_vals[base + (size_t)row * 144 + col] = acc[r][j] + b2e[col];
        }
    }
}

// ---------------------------------------------------------
// K2: zero messages
// ---------------------------------------------------------
__global__ void k_zero() {
    int idx = blockIdx.x * blockDim.x + threadIdx.x;
    if (idx < Bq * Ee * Aa) { g_msg_forw[idx] = 0.f; g_msg_back[idx] = 0.f; }
}

// ---------------------------------------------------------
// K3: init q = node_vals/N, a = argmax(node_vals), qmax = -inf
// ---------------------------------------------------------
__global__ void k_init() {
    int idx = blockIdx.x * blockDim.x + threadIdx.x;
    if (idx < Bq * Nn) {
        float best = -3.4e38f; int ba = 0;
#pragma unroll
        for (int a = 0; a < 12; a++) {
            float v = g_node_vals[idx * 12 + a];
            g_q[idx * 12 + a] = v * (1.f / Nn);
            if (v > best) { best = v; ba = a; }
        }
        g_a[idx] = ba;
    }
    if (idx < Bq) g_qmax[idx] = -3.4e38f;
}

// ---------------------------------------------------------
// K4: message update. Block = 16 edges. Reads edge block once,
// computes both forw (col-max) and back (row-max) messages + mean-norm.
// ---------------------------------------------------------
__global__ void k_msg(const int* __restrict__ ef, const int* __restrict__ et) {
    int b = blockIdx.y;
    int e0 = blockIdx.x * 16;
    int tid = threadIdx.x;
    __shared__ float ev[16 * 144];
    __shared__ float su[192], sv[192], smf[192], smb[192];

    const float* src = &g_edge_vals[((size_t)b * Ee + e0) * 144];
    for (int i = tid; i < 16 * 144; i += 256) ev[i] = src[i];
    if (tid < 192) {
        int el = tid / 12, a = tid - el * 12;
        int e = e0 + el;
        int f = ef[e], t = et[e];
        int mi = (b * Ee + e) * 12 + a;
        su[tid] = g_q[(b * Nn + f) * 12 + a] - g_msg_back[mi];
        sv[tid] = g_q[(b * Nn + t) * 12 + a] - g_msg_forw[mi];
    }
    __syncthreads();
    if (tid < 192) {
        int el = tid / 12, a = tid - el * 12;
        const float invE = 1.f / Ee;
        float mf = -3.4e38f, mb = -3.4e38f;
#pragma unroll
        for (int x = 0; x < 12; x++) {
            mf = fmaxf(mf, su[el * 12 + x] + ev[el * 144 + x * 12 + a] * invE);
            mb = fmaxf(mb, sv[el * 12 + x] + ev[el * 144 + a * 12 + x] * invE);
        }
        smf[tid] = mf; smb[tid] = mb;
    }
    __syncthreads();
    if (tid < 192) {
        int el = tid / 12;
        float sfo = 0.f, sba = 0.f;
#pragma unroll
        for (int x = 0; x < 12; x++) { sfo += smf[el * 12 + x]; sba += smb[el * 12 + x]; }
        int mi = (b * Ee + e0 + el) * 12 + (tid - el * 12);
        g_msg_forw[mi] = smf[tid] - sfo * (1.f / 12.f);
        g_msg_back[mi] = smb[tid] - sba * (1.f / 12.f);
    }
}

// ---------------------------------------------------------
// K5: q update + argmax. One warp per (b,n); deterministic gather
// (no atomics). Incoming forw edges: e = i*63 + (n - (n>i)).
// Outgoing back edges: contiguous [n*63, n*63+63).
// ---------------------------------------------------------
__global__ void k_qup() {
    int gw = (blockIdx.x * blockDim.x + threadIdx.x) >> 5;
    int lane = threadIdx.x & 31;
    int b = gw >> 6, n = gw & 63;
    float acc[12];
#pragma unroll
    for (int a = 0; a < 12; a++) acc[a] = 0.f;

    size_t mb_base = ((size_t)b * Ee + n * 63) * 12;
    for (int m = lane; m < 63; m += 32) {
        const float4* p = (const float4*)&g_msg_back[mb_base + m * 12];
        float4 p0 = p[0], p1 = p[1], p2 = p[2];
        acc[0] += p0.x; acc[1] += p0.y; acc[2]  += p0.z; acc[3]  += p0.w;
        acc[4] += p1.x; acc[5] += p1.y; acc[6]  += p1.z; acc[7]  += p1.w;
        acc[8] += p2.x; acc[9] += p2.y; acc[10] += p2.z; acc[11] += p2.w;
    }
    for (int i = lane; i < 64; i += 32) {
        if (i == n) continue;
        int e = i * 63 + n - (n > i ? 1 : 0);
        const float4* p = (const float4*)&g_msg_forw[((size_t)b * Ee + e) * 12];
        float4 p0 = p[0], p1 = p[1], p2 = p[2];
        acc[0] += p0.x; acc[1] += p0.y; acc[2]  += p0.z; acc[3]  += p0.w;
        acc[4] += p1.x; acc[5] += p1.y; acc[6]  += p1.z; acc[7]  += p1.w;
        acc[8] += p2.x; acc[9] += p2.y; acc[10] += p2.z; acc[11] += p2.w;
    }
#pragma unroll
    for (int off = 16; off; off >>= 1)
#pragma unroll
        for (int a = 0; a < 12; a++) acc[a] += __shfl_down_sync(0xffffffffu, acc[a], off);

    if (lane == 0) {
        float best = -3.4e38f; int ba = 0;
#pragma unroll
        for (int a = 0; a < 12; a++) {
            float qa = g_node_vals[gw * 12 + a] * (1.f / Nn) + acc[a];
            g_q[gw * 12 + a] = qa;
            if (qa > best) { best = qa; ba = a; }
        }
        g_a[gw] = ba;
    }
}

// ---------------------------------------------------------
// K6: evaluate current assignment per batch, track running max,
// write q_max + a_max into output (float layout: [128 | 128*64]).
// ---------------------------------------------------------
__global__ void k_eval(const int* __restrict__ ef, const int* __restrict__ et,
                       float* __restrict__ out, int first) {
    int b = blockIdx.x, tid = threadIdx.x;
    __shared__ int sa[64];
    __shared__ float red[256];
    __shared__ int flag;
    if (tid < 64) sa[tid] = g_a[b * 64 + tid];
    __syncthreads();

    float s = 0.f;
    for (int e = tid; e < Ee; e += 256) {
        int f = ef[e], t = et[e];
        s += g_edge_vals[((size_t)b * Ee + e) * 144 + sa[f] * 12 + sa[t]];
    }
    red[tid] = s; __syncthreads();
    for (int o = 128; o; o >>= 1) { if (tid < o) red[tid] += red[tid + o]; __syncthreads(); }
    float es = red[0];
    __syncthreads();

    float ns = 0.f;
    if (tid < 64) ns = g_node_vals[(b * 64 + tid) * 12 + sa[tid]];
    red[tid] = ns; __syncthreads();
    for (int o = 128; o; o >>= 1) { if (tid < o) red[tid] += red[tid + o]; __syncthreads(); }

    if (tid == 0) {
        float qv = red[0] / (float)Nn + es / (float)Ee;
        int up = first || (qv > g_qmax[b]);
        if (up) g_qmax[b] = qv;
        out[b] = g_qmax[b];
        flag = up;
    }
    __syncthreads();
    if (flag && tid < 64) out[Bq + b * 64 + tid] = (float)sa[tid];
}

// ---------------------------------------------------------
extern "C" void kernel_launch(void* const* d_in, const int* in_sizes, int n_in,
                              void* d_out, int out_size) {
    const float* obs = (const float*)d_in[0];
    const float* W1n = (const float*)d_in[1];
    const float* b1n = (const float*)d_in[2];
    const float* W2n = (const float*)d_in[3];
    const float* b2n = (const float*)d_in[4];
    const float* W1e = (const float*)d_in[5];
    const float* b1e = (const float*)d_in[6];
    const float* W2e = (const float*)d_in[7];
    const float* b2e = (const float*)d_in[8];
    const int* ef = (const int*)d_in[9];
    const int* et = (const int*)d_in[10];
    float* out = (float*)d_out;

    const int gemm_smem = (128 * 144 + 64 * 132) * 4;   // 107520 B
    cudaFuncSetAttribute(k_edge_gemm, cudaFuncAttributeMaxDynamicSharedMemorySize, gemm_smem);

    k_node<<<Bq * Nn / 8, 128>>>(obs, W1n, b1n, W2n, b2n, W1e);
    k_edge_gemm<<<dim3(Ee / 64, Bq), 256, gemm_smem>>>(ef, et, b1e, W2e, b2e);
    k_zero<<<(Bq * Ee * Aa + 255) / 256, 256>>>();
    k_init<<<(Bq * Nn + 255) / 256, 256>>>();
    k_eval<<<Bq, 256>>>(ef, et, out, 1);
    for (int it = 0; it < NITERS; it++) {
        k_msg<<<dim3(Ee / 16, Bq), 256>>>(ef, et);
        k_qup<<<(Bq * Nn * 32) / 256, 256>>>();
        k_eval<<<Bq, 256>>>(ef, et, out, 0);
    }
}

// round 3
// speedup vs baseline: 1.2619x; 1.2619x over previous
#include <cuda_runtime.h>

#define Bq 128
#define Nn 64
#define Dd 64
#define Aa 12
#define Hh 128
#define Ee 4032
#define NITERS 8
#define TE 96   // edges per gemm block

typedef unsigned long long ull;

// -------- device scratch (no allocations allowed) --------
__device__ __align__(16) float g_edge_vals[74317824];   // B*E*A*A (~297MB)
__device__ __align__(16) float g_X1[Bq*Nn*Hh];
__device__ __align__(16) float g_X2[Bq*Nn*Hh];
__device__ float g_node_vals[Bq*Nn*Aa];
__device__ float g_q[Bq*Nn*Aa];
__device__ __align__(16) float g_msg_forw[Bq*Ee*Aa];
__device__ __align__(16) float g_msg_back[Bq*Ee*Aa];
__device__ int   g_a[Bq*Nn];
__device__ float g_qmax[Bq];

// ---------------------------------------------------------
// K0: node MLP + per-node halves of edge layer-1 (X1, X2)
// ---------------------------------------------------------
__global__ void k_node(const float* __restrict__ obs, const float* __restrict__ W1n,
                       const float* __restrict__ b1n, const float* __restrict__ W2n,
                       const float* __restrict__ b2n, const float* __restrict__ W1e) {
    int row0 = blockIdx.x * 8;
    int t = threadIdx.x;
    __shared__ float so[8][64];
    __shared__ float sh[8][128];
    for (int i = t; i < 512; i += 128) so[i >> 6][i & 63] = obs[row0 * 64 + i];
    __syncthreads();
    for (int r = 0; r < 8; r++) {
        float s1 = b1n[t], x1 = 0.f, x2 = 0.f;
#pragma unroll 8
        for (int d = 0; d < 64; d++) {
            float o = so[r][d];
            s1 = fmaf(o, W1n[d * 128 + t], s1);
            x1 = fmaf(o, W1e[d * 128 + t], x1);
            x2 = fmaf(o, W1e[(64 + d) * 128 + t], x2);
        }
        sh[r][t] = fmaxf(s1, 0.f);
        g_X1[(row0 + r) * 128 + t] = x1;
        g_X2[(row0 + r) * 128 + t] = x2;
    }
    __syncthreads();
    if (t < 96) {
        int r = t / 12, a = t - r * 12;
        float nv = b2n[a];
#pragma unroll 8
        for (int k = 0; k < 128; k++) nv = fmaf(sh[r][k], W2n[k * 12 + a], nv);
        g_node_vals[(row0 + r) * 12 + a] = nv;
    }
}

// ---------------------------------------------------------
// K1: edge layer-2 GEMM, f32x2 packed FMA.
// Block = 96 edges x 144 cols, 384 threads.
// hT: k-major transposed hidden tile (pitch 100) -> row-pairs load as LDS.64.
// Each thread: 12 rows (6 row-pairs) x 3 cols = 18 f32x2 accumulators.
// ---------------------------------------------------------
__global__ void __launch_bounds__(384)
k_edge_gemm(const int* __restrict__ ef, const int* __restrict__ et,
            const float* __restrict__ b1e, const float* __restrict__ W2e,
            const float* __restrict__ b2e) {
    extern __shared__ float sm[];
    float* Wsh = sm;                 // 128*144 floats
    float* hT  = sm + 18432;         // 128 * 100 floats (pitch 100)
    __shared__ int sf[TE], st2[TE];
    int b = blockIdx.y;
    int e0 = blockIdx.x * TE;
    int tid = threadIdx.x;

    if (tid < TE) { sf[tid] = ef[e0 + tid]; st2[tid] = et[e0 + tid]; }
    {   // W2e -> smem, vectorized
        const float4* W4 = (const float4*)W2e;
        float4* Ws4 = (float4*)Wsh;
        for (int i = tid; i < 4608; i += 384) Ws4[i] = W4[i];
    }
    __syncthreads();

    // fill hT[k][el] = relu(X1[sf[el]][k] + X2[st[el]][k] + b1e[k])
#pragma unroll 4
    for (int s = 0; s < 32; s++) {
        int idx = s * 384 + tid;
        int el = idx >> 7, k = idx & 127;
        float v = g_X1[(b * Nn + sf[el]) * Hh + k] + g_X2[(b * Nn + st2[el]) * Hh + k] + b1e[k];
        hT[k * 100 + el] = fmaxf(v, 0.f);
    }
    __syncthreads();

    int rg = tid / 48;     // 0..7  -> rows rg*12 .. rg*12+11
    int cg = tid % 48;     // 0..47 -> cols cg*3 .. cg*3+2

    ull acc[6][3];
#pragma unroll
    for (int j = 0; j < 6; j++)
#pragma unroll
        for (int c = 0; c < 3; c++) acc[j][c] = 0ull;

    const float* hrow = hT + rg * 12;
    const float* wcol = Wsh + cg * 3;

#pragma unroll 8
    for (int k = 0; k < 128; k++) {
        ull hv[6];
#pragma unroll
        for (int j = 0; j < 6; j++)
            hv[j] = *(const ull*)(hrow + k * 100 + 2 * j);   // LDS.64: (row2j, row2j+1)
        ull wv[3];
#pragma unroll
        for (int c = 0; c < 3; c++) {
            float w = wcol[k * 144 + c];
            asm("mov.b64 %0, {%1, %1};" : "=l"(wv[c]) : "f"(w));   // splat
        }
#pragma unroll
        for (int j = 0; j < 6; j++)
#pragma unroll
            for (int c = 0; c < 3; c++)
                asm("fma.rn.f32x2 %0, %1, %2, %0;" : "+l"(acc[j][c]) : "l"(hv[j]), "l"(wv[c]));
    }

    float bb[3];
#pragma unroll
    for (int c = 0; c < 3; c++) bb[c] = b2e[cg * 3 + c];

    size_t base = ((size_t)b * Ee + e0) * 144 + cg * 3;
#pragma unroll
    for (int j = 0; j < 6; j++) {
        int row = rg * 12 + 2 * j;
#pragma unroll
        for (int c = 0; c < 3; c++) {
            float lo, hi;
            asm("mov.b64 {%0, %1}, %2;" : "=f"(lo), "=f"(hi) : "l"(acc[j][c]));
            g_edge_vals[base + (size_t)row * 144 + c]       = lo + bb[c];
            g_edge_vals[base + (size_t)(row + 1) * 144 + c] = hi + bb[c];
        }
    }
}

// ---------------------------------------------------------
// K2: zero messages (vectorized)
// ---------------------------------------------------------
__global__ void k_zero() {
    int idx = blockIdx.x * blockDim.x + threadIdx.x;
    float4 z = make_float4(0.f, 0.f, 0.f, 0.f);
    if (idx < (Bq * Ee * Aa) / 4) {
        ((float4*)g_msg_forw)[idx] = z;
        ((float4*)g_msg_back)[idx] = z;
    }
}

// ---------------------------------------------------------
// K3: init q = node_vals/N, a = argmax(node_vals)
// ---------------------------------------------------------
__global__ void k_init() {
    int idx = blockIdx.x * blockDim.x + threadIdx.x;
    if (idx < Bq * Nn) {
        float best = -3.4e38f; int ba = 0;
#pragma unroll
        for (int a = 0; a < 12; a++) {
            float v = g_node_vals[idx * 12 + a];
            g_q[idx * 12 + a] = v * (1.f / Nn);
            if (v > best) { best = v; ba = a; }
        }
        g_a[idx] = ba;
    }
}

// ---------------------------------------------------------
// K4: message update. 32 edges/block, 512 threads.
// ev staged to smem pre-scaled by 1/E (float4).
// ---------------------------------------------------------
__global__ void __launch_bounds__(512)
k_msg(const int* __restrict__ ef, const int* __restrict__ et) {
    int b = blockIdx.y;
    int e0 = blockIdx.x * 32;
    int tid = threadIdx.x;
    __shared__ float evs[32 * 144];
    __shared__ float su[384], sv[384], smf[384], smb[384];

    const float4* src = (const float4*)&g_edge_vals[((size_t)b * Ee + e0) * 144];
    float4* dst = (float4*)evs;
    const float invE = 1.f / Ee;
#pragma unroll
    for (int i = tid; i < 1152; i += 512) {
        float4 v = src[i];
        v.x *= invE; v.y *= invE; v.z *= invE; v.w *= invE;
        dst[i] = v;
    }
    if (tid < 384) {
        int el = tid / 12, a = tid - el * 12;
        int e = e0 + el;
        int f = ef[e], t = et[e];
        size_t mi = ((size_t)b * Ee + e) * 12 + a;
        su[tid] = g_q[(b * Nn + f) * 12 + a] - g_msg_back[mi];
        sv[tid] = g_q[(b * Nn + t) * 12 + a] - g_msg_forw[mi];
    }
    __syncthreads();
    if (tid < 384) {
        int el = tid / 12, a = tid - el * 12;
        const float* evb = &evs[el * 144];
        const float* sub = &su[el * 12];
        const float* svb = &sv[el * 12];
        float mf = -3.4e38f, mb = -3.4e38f;
#pragma unroll
        for (int x = 0; x < 12; x++) {
            mf = fmaxf(mf, sub[x] + evb[x * 12 + a]);
            mb = fmaxf(mb, svb[x] + evb[a * 12 + x]);
        }
        smf[tid] = mf; smb[tid] = mb;
    }
    __syncthreads();
    if (tid < 384) {
        int el = tid / 12, a = tid - el * 12;
        float sfo = 0.f, sba = 0.f;
#pragma unroll
        for (int x = 0; x < 12; x++) { sfo += smf[el * 12 + x]; sba += smb[el * 12 + x]; }
        size_t mi = ((size_t)b * Ee + e0 + el) * 12 + a;
        g_msg_forw[mi] = smf[tid] - sfo * (1.f / 12.f);
        g_msg_back[mi] = smb[tid] - sba * (1.f / 12.f);
    }
}

// ---------------------------------------------------------
// K5: q update + argmax. One warp per (b,n); deterministic gather.
// ---------------------------------------------------------
__global__ void k_qup() {
    int gw = (blockIdx.x * blockDim.x + threadIdx.x) >> 5;
    int lane = threadIdx.x & 31;
    int b = gw >> 6, n = gw & 63;
    float acc[12];
#pragma unroll
    for (int a = 0; a < 12; a++) acc[a] = 0.f;

    size_t mb_base = ((size_t)b * Ee + n * 63) * 12;
    for (int m = lane; m < 63; m += 32) {
        const float4* p = (const float4*)&g_msg_back[mb_base + m * 12];
        float4 p0 = p[0], p1 = p[1], p2 = p[2];
        acc[0] += p0.x; acc[1] += p0.y; acc[2]  += p0.z; acc[3]  += p0.w;
        acc[4] += p1.x; acc[5] += p1.y; acc[6]  += p1.z; acc[7]  += p1.w;
        acc[8] += p2.x; acc[9] += p2.y; acc[10] += p2.z; acc[11] += p2.w;
    }
    for (int i = lane; i < 64; i += 32) {
        if (i == n) continue;
        int e = i * 63 + n - (n > i ? 1 : 0);
        const float4* p = (const float4*)&g_msg_forw[((size_t)b * Ee + e) * 12];
        float4 p0 = p[0], p1 = p[1], p2 = p[2];
        acc[0] += p0.x; acc[1] += p0.y; acc[2]  += p0.z; acc[3]  += p0.w;
        acc[4] += p1.x; acc[5] += p1.y; acc[6]  += p1.z; acc[7]  += p1.w;
        acc[8] += p2.x; acc[9] += p2.y; acc[10] += p2.z; acc[11] += p2.w;
    }
#pragma unroll
    for (int off = 16; off; off >>= 1)
#pragma unroll
        for (int a = 0; a < 12; a++) acc[a] += __shfl_down_sync(0xffffffffu, acc[a], off);

    if (lane == 0) {
        float best = -3.4e38f; int ba = 0;
#pragma unroll
        for (int a = 0; a < 12; a++) {
            float qa = g_node_vals[gw * 12 + a] * (1.f / Nn) + acc[a];
            g_q[gw * 12 + a] = qa;
            if (qa > best) { best = qa; ba = a; }
        }
        g_a[gw] = ba;
    }
}

// ---------------------------------------------------------
// K6: evaluate assignment per batch, track max, write output.
// 1024 threads/block for memory-level parallelism on the gathers.
// ---------------------------------------------------------
__global__ void __launch_bounds__(1024)
k_eval(const int* __restrict__ ef, const int* __restrict__ et,
       float* __restrict__ out, int first) {
    int b = blockIdx.x, tid = threadIdx.x;
    __shared__ int sa[64];
    __shared__ float red[1024];
    __shared__ int flag;
    if (tid < 64) sa[tid] = g_a[b * 64 + tid];
    __syncthreads();

    float s = 0.f;
#pragma unroll
    for (int e = tid; e < Ee; e += 1024)
        s += g_edge_vals[((size_t)b * Ee + e) * 144 + sa[ef[e]] * 12 + sa[et[e]]];
    red[tid] = s; __syncthreads();
    for (int o = 512; o; o >>= 1) { if (tid < o) red[tid] += red[tid + o]; __syncthreads(); }
    float es = red[0];
    __syncthreads();

    red[tid] = (tid < 64) ? g_node_vals[(b * 64 + tid) * 12 + sa[tid]] : 0.f;
    __syncthreads();
    for (int o = 512; o; o >>= 1) { if (tid < o) red[tid] += red[tid + o]; __syncthreads(); }

    if (tid == 0) {
        float qv = red[0] / (float)Nn + es / (float)Ee;
        int up = first || (qv > g_qmax[b]);
        if (up) g_qmax[b] = qv;
        out[b] = g_qmax[b];
        flag = up;
    }
    __syncthreads();
    if (flag && tid < 64) out[Bq + b * 64 + tid] = (float)sa[tid];
}

// ---------------------------------------------------------
extern "C" void kernel_launch(void* const* d_in, const int* in_sizes, int n_in,
                              void* d_out, int out_size) {
    const float* obs = (const float*)d_in[0];
    const float* W1n = (const float*)d_in[1];
    const float* b1n = (const float*)d_in[2];
    const float* W2n = (const float*)d_in[3];
    const float* b2n = (const float*)d_in[4];
    const float* W1e = (const float*)d_in[5];
    const float* b1e = (const float*)d_in[6];
    const float* W2e = (const float*)d_in[7];
    const float* b2e = (const float*)d_in[8];
    const int* ef = (const int*)d_in[9];
    const int* et = (const int*)d_in[10];
    float* out = (float*)d_out;

    const int gemm_smem = (18432 + 12800) * 4;   // 124928 B
    cudaFuncSetAttribute(k_edge_gemm, cudaFuncAttributeMaxDynamicSharedMemorySize, gemm_smem);

    k_node<<<Bq * Nn / 8, 128>>>(obs, W1n, b1n, W2n, b2n, W1e);
    k_edge_gemm<<<dim3(Ee / TE, Bq), 384, gemm_smem>>>(ef, et, b1e, W2e, b2e);
    k_zero<<<(Bq * Ee * Aa / 4 + 255) / 256, 256>>>();
    k_init<<<(Bq * Nn + 255) / 256, 256>>>();
    k_eval<<<Bq, 1024>>>(ef, et, out, 1);
    for (int it = 0; it < NITERS; it++) {
        k_msg<<<dim3(Ee / 32, Bq), 512>>>(ef, et);
        k_qup<<<(Bq * Nn * 32) / 256, 256>>>();
        k_eval<<<Bq, 1024>>>(ef, et, out, 0);
    }
}

// round 4
// speedup vs baseline: 1.3159x; 1.0429x over previous
#include <cuda_runtime.h>

#define Bq 128
#define Nn 64
#define Dd 64
#define Aa 12
#define Hh 128
#define Ee 4032
#define NITERS 8
#define TE 96   // edges per gemm block

typedef unsigned long long ull;

// -------- device scratch (no allocations allowed) --------
__device__ __align__(16) float g_edge_vals[74317824];   // B*E*A*A (~297MB)
__device__ __align__(16) float g_X1[Bq*Nn*Hh];
__device__ __align__(16) float g_X2[Bq*Nn*Hh];
__device__ float g_node_vals[Bq*Nn*Aa];
__device__ float g_q[Bq*Nn*Aa];
__device__ __align__(16) float g_msg_forw[Bq*Ee*Aa];
__device__ __align__(16) float g_msg_back[Bq*Ee*Aa];
__device__ float g_qmax[Bq];

// ---------------------------------------------------------
// K0: node MLP + per-node halves of edge layer-1 (X1, X2)
// ---------------------------------------------------------
__global__ void k_node(const float* __restrict__ obs, const float* __restrict__ W1n,
                       const float* __restrict__ b1n, const float* __restrict__ W2n,
                       const float* __restrict__ b2n, const float* __restrict__ W1e) {
    int row0 = blockIdx.x * 8;
    int t = threadIdx.x;
    __shared__ float so[8][64];
    __shared__ float sh[8][128];
    for (int i = t; i < 512; i += 128) so[i >> 6][i & 63] = obs[row0 * 64 + i];
    __syncthreads();
    for (int r = 0; r < 8; r++) {
        float s1 = b1n[t], x1 = 0.f, x2 = 0.f;
#pragma unroll 8
        for (int d = 0; d < 64; d++) {
            float o = so[r][d];
            s1 = fmaf(o, W1n[d * 128 + t], s1);
            x1 = fmaf(o, W1e[d * 128 + t], x1);
            x2 = fmaf(o, W1e[(64 + d) * 128 + t], x2);
        }
        sh[r][t] = fmaxf(s1, 0.f);
        g_X1[(row0 + r) * 128 + t] = x1;
        g_X2[(row0 + r) * 128 + t] = x2;
    }
    __syncthreads();
    if (t < 96) {
        int r = t / 12, a = t - r * 12;
        float nv = b2n[a];
#pragma unroll 8
        for (int k = 0; k < 128; k++) nv = fmaf(sh[r][k], W2n[k * 12 + a], nv);
        g_node_vals[(row0 + r) * 12 + a] = nv;
    }
}

// ---------------------------------------------------------
// K1: edge layer-2 GEMM, f32x2 packed FMA.
// ---------------------------------------------------------
__global__ void __launch_bounds__(384)
k_edge_gemm(const int* __restrict__ ef, const int* __restrict__ et,
            const float* __restrict__ b1e, const float* __restrict__ W2e,
            const float* __restrict__ b2e) {
    extern __shared__ float sm[];
    float* Wsh = sm;                 // 128*144 floats
    float* hT  = sm + 18432;         // 128 * 100 floats (pitch 100)
    __shared__ int sf[TE], st2[TE];
    int b = blockIdx.y;
    int e0 = blockIdx.x * TE;
    int tid = threadIdx.x;

    if (tid < TE) { sf[tid] = ef[e0 + tid]; st2[tid] = et[e0 + tid]; }
    {
        const float4* W4 = (const float4*)W2e;
        float4* Ws4 = (float4*)Wsh;
        for (int i = tid; i < 4608; i += 384) Ws4[i] = W4[i];
    }
    __syncthreads();

#pragma unroll 4
    for (int s = 0; s < 32; s++) {
        int idx = s * 384 + tid;
        int el = idx >> 7, k = idx & 127;
        float v = g_X1[(b * Nn + sf[el]) * Hh + k] + g_X2[(b * Nn + st2[el]) * Hh + k] + b1e[k];
        hT[k * 100 + el] = fmaxf(v, 0.f);
    }
    __syncthreads();

    int rg = tid / 48;
    int cg = tid % 48;

    ull acc[6][3];
#pragma unroll
    for (int j = 0; j < 6; j++)
#pragma unroll
        for (int c = 0; c < 3; c++) acc[j][c] = 0ull;

    const float* hrow = hT + rg * 12;
    const float* wcol = Wsh + cg * 3;

#pragma unroll 8
    for (int k = 0; k < 128; k++) {
        ull hv[6];
#pragma unroll
        for (int j = 0; j < 6; j++)
            hv[j] = *(const ull*)(hrow + k * 100 + 2 * j);
        ull wv[3];
#pragma unroll
        for (int c = 0; c < 3; c++) {
            float w = wcol[k * 144 + c];
            asm("mov.b64 %0, {%1, %1};" : "=l"(wv[c]) : "f"(w));
        }
#pragma unroll
        for (int j = 0; j < 6; j++)
#pragma unroll
            for (int c = 0; c < 3; c++)
                asm("fma.rn.f32x2 %0, %1, %2, %0;" : "+l"(acc[j][c]) : "l"(hv[j]), "l"(wv[c]));
    }

    float bb[3];
#pragma unroll
    for (int c = 0; c < 3; c++) bb[c] = b2e[cg * 3 + c];

    size_t base = ((size_t)b * Ee + e0) * 144 + cg * 3;
#pragma unroll
    for (int j = 0; j < 6; j++) {
        int row = rg * 12 + 2 * j;
#pragma unroll
        for (int c = 0; c < 3; c++) {
            float lo, hi;
            asm("mov.b64 {%0, %1}, %2;" : "=f"(lo), "=f"(hi) : "l"(acc[j][c]));
            g_edge_vals[base + (size_t)row * 144 + c]       = lo + bb[c];
            g_edge_vals[base + (size_t)(row + 1) * 144 + c] = hi + bb[c];
        }
    }
}

// ---------------------------------------------------------
// K2a/K2b: zero message arrays (split so gemm sits at launch idx 3)
// ---------------------------------------------------------
__global__ void k_zf() {
    int idx = blockIdx.x * blockDim.x + threadIdx.x;
    if (idx < (Bq * Ee * Aa) / 4) ((float4*)g_msg_forw)[idx] = make_float4(0.f, 0.f, 0.f, 0.f);
}
__global__ void k_zb() {
    int idx = blockIdx.x * blockDim.x + threadIdx.x;
    if (idx < (Bq * Ee * Aa) / 4) ((float4*)g_msg_back)[idx] = make_float4(0.f, 0.f, 0.f, 0.f);
}

// ---------------------------------------------------------
// K4: message update. 64 edges/block, 768 threads (= 64*12, all compute).
// ---------------------------------------------------------
__global__ void __launch_bounds__(768)
k_msg(const int* __restrict__ ef, const int* __restrict__ et) {
    int b = blockIdx.y;
    int e0 = blockIdx.x * 64;
    int tid = threadIdx.x;
    __shared__ float evs[64 * 144];
    __shared__ float su[768], sv[768], smf[768], smb[768];

    const float4* src = (const float4*)&g_edge_vals[((size_t)b * Ee + e0) * 144];
    float4* dst = (float4*)evs;
    const float invE = 1.f / Ee;
#pragma unroll
    for (int i = 0; i < 3; i++) {
        int idx = tid + i * 768;
        float4 v = src[idx];
        v.x *= invE; v.y *= invE; v.z *= invE; v.w *= invE;
        dst[idx] = v;
    }
    int el = tid / 12, a = tid - el * 12;
    int e = e0 + el;
    int f = ef[e], t = et[e];
    size_t mi = ((size_t)b * Ee + e) * 12 + a;
    su[tid] = g_q[(b * Nn + f) * 12 + a] - g_msg_back[mi];
    sv[tid] = g_q[(b * Nn + t) * 12 + a] - g_msg_forw[mi];
    __syncthreads();

    const float* evb = &evs[el * 144];
    const float* sub = &su[el * 12];
    const float* svb = &sv[el * 12];
    float mf = -3.4e38f, mb = -3.4e38f;
#pragma unroll
    for (int x = 0; x < 12; x++) {
        mf = fmaxf(mf, sub[x] + evb[x * 12 + a]);
        mb = fmaxf(mb, svb[x] + evb[a * 12 + x]);
    }
    smf[tid] = mf; smb[tid] = mb;
    __syncthreads();

    float sfo = 0.f, sba = 0.f;
#pragma unroll
    for (int x = 0; x < 12; x++) { sfo += smf[el * 12 + x]; sba += smb[el * 12 + x]; }
    g_msg_forw[mi] = mf - sfo * (1.f / 12.f);
    g_msg_back[mi] = mb - sba * (1.f / 12.f);
}

// ---------------------------------------------------------
// K5: fused q-update + argmax + eval + running-max + output.
// One block per batch, 1024 threads. first=1 also does the init path.
// q-update accumulation order identical to the previously-passing k_qup.
// ---------------------------------------------------------
__global__ void __launch_bounds__(1024)
k_qe(const int* __restrict__ ef, const int* __restrict__ et,
     float* __restrict__ out, int first) {
    int b = blockIdx.x, tid = threadIdx.x;
    int w = tid >> 5, lane = tid & 31;
    __shared__ float snv[768];
    __shared__ int sa[64];
    __shared__ float red[1024];
    __shared__ int flag;
    for (int i = tid; i < 768; i += 1024) snv[i] = g_node_vals[b * 768 + i];
    __syncthreads();

    if (first) {
        if (tid < 768) g_q[b * 768 + tid] = snv[tid] * (1.f / Nn);
        if (tid < 64) {
            float best = -3.4e38f; int ba = 0;
#pragma unroll
            for (int a = 0; a < 12; a++) {
                float v = snv[tid * 12 + a];
                if (v > best) { best = v; ba = a; }
            }
            sa[tid] = ba;
        }
    } else {
#pragma unroll
        for (int nn = 0; nn < 2; nn++) {
            int n = w * 2 + nn;
            float acc[12];
#pragma unroll
            for (int a = 0; a < 12; a++) acc[a] = 0.f;

            size_t mbb = ((size_t)b * Ee + n * 63) * 12;
            for (int m = lane; m < 63; m += 32) {
                const float4* p = (const float4*)&g_msg_back[mbb + m * 12];
                float4 p0 = p[0], p1 = p[1], p2 = p[2];
                acc[0] += p0.x; acc[1] += p0.y; acc[2]  += p0.z; acc[3]  += p0.w;
                acc[4] += p1.x; acc[5] += p1.y; acc[6]  += p1.z; acc[7]  += p1.w;
                acc[8] += p2.x; acc[9] += p2.y; acc[10] += p2.z; acc[11] += p2.w;
            }
            for (int i = lane; i < 64; i += 32) {
                if (i == n) continue;
                int e = i * 63 + n - (n > i ? 1 : 0);
                const float4* p = (const float4*)&g_msg_forw[((size_t)b * Ee + e) * 12];
                float4 p0 = p[0], p1 = p[1], p2 = p[2];
                acc[0] += p0.x; acc[1] += p0.y; acc[2]  += p0.z; acc[3]  += p0.w;
                acc[4] += p1.x; acc[5] += p1.y; acc[6]  += p1.z; acc[7]  += p1.w;
                acc[8] += p2.x; acc[9] += p2.y; acc[10] += p2.z; acc[11] += p2.w;
            }
#pragma unroll
            for (int off = 16; off; off >>= 1)
#pragma unroll
                for (int a = 0; a < 12; a++) acc[a] += __shfl_down_sync(0xffffffffu, acc[a], off);

            if (lane == 0) {
                float best = -3.4e38f; int ba = 0;
#pragma unroll
                for (int a = 0; a < 12; a++) {
                    float qa = snv[n * 12 + a] * (1.f / Nn) + acc[a];
                    g_q[(b * 64 + n) * 12 + a] = qa;
                    if (qa > best) { best = qa; ba = a; }
                }
                sa[n] = ba;
            }
        }
    }
    __syncthreads();

    // eval current assignment
    float s = 0.f;
#pragma unroll
    for (int e = tid; e < Ee; e += 1024)
        s += g_edge_vals[((size_t)b * Ee + e) * 144 + sa[ef[e]] * 12 + sa[et[e]]];
    red[tid] = s; __syncthreads();
    for (int o = 512; o; o >>= 1) { if (tid < o) red[tid] += red[tid + o]; __syncthreads(); }
    float es = red[0];
    __syncthreads();

    red[tid] = (tid < 64) ? snv[tid * 12 + sa[tid]] : 0.f;
    __syncthreads();
    for (int o = 512; o; o >>= 1) { if (tid < o) red[tid] += red[tid + o]; __syncthreads(); }

    if (tid == 0) {
        float qv = red[0] / (float)Nn + es / (float)Ee;
        int up = first || (qv > g_qmax[b]);
        if (up) g_qmax[b] = qv;
        out[b] = g_qmax[b];
        flag = up;
    }
    __syncthreads();
    if (flag && tid < 64) out[Bq + b * 64 + tid] = (float)sa[tid];
}

// ---------------------------------------------------------
extern "C" void kernel_launch(void* const* d_in, const int* in_sizes, int n_in,
                              void* d_out, int out_size) {
    const float* obs = (const float*)d_in[0];
    const float* W1n = (const float*)d_in[1];
    const float* b1n = (const float*)d_in[2];
    const float* W2n = (const float*)d_in[3];
    const float* b2n = (const float*)d_in[4];
    const float* W1e = (const float*)d_in[5];
    const float* b1e = (const float*)d_in[6];
    const float* W2e = (const float*)d_in[7];
    const float* b2e = (const float*)d_in[8];
    const int* ef = (const int*)d_in[9];
    const int* et = (const int*)d_in[10];
    float* out = (float*)d_out;

    const int gemm_smem = (18432 + 12800) * 4;   // 124928 B
    cudaFuncSetAttribute(k_edge_gemm, cudaFuncAttributeMaxDynamicSharedMemorySize, gemm_smem);

    int zgrid = (Bq * Ee * Aa / 4 + 255) / 256;
    k_node<<<Bq * Nn / 8, 128>>>(obs, W1n, b1n, W2n, b2n, W1e);        // idx 0
    k_zf<<<zgrid, 256>>>();                                            // idx 1
    k_zb<<<zgrid, 256>>>();                                            // idx 2
    k_edge_gemm<<<dim3(Ee / TE, Bq), 384, gemm_smem>>>(ef, et, b1e, W2e, b2e);  // idx 3 (profiled)
    k_qe<<<Bq, 1024>>>(ef, et, out, 1);                                // idx 4
    for (int it = 0; it < NITERS; it++) {
        k_msg<<<dim3(Ee / 64, Bq), 768>>>(ef, et);
        k_qe<<<Bq, 1024>>>(ef, et, out, 0);
    }
}

// round 5
// speedup vs baseline: 1.3432x; 1.0207x over previous
#include <cuda_runtime.h>

#define Bq 128
#define Nn 64
#define Dd 64
#define Aa 12
#define Hh 128
#define Ee 4032
#define NITERS 8
#define TE 64   // edges per gemm block

typedef unsigned long long ull;

// -------- device scratch (no allocations allowed) --------
__device__ __align__(16) float g_edge_vals[74317824];   // B*E*A*A (~297MB)
__device__ __align__(16) float g_X1[Bq*Nn*Hh];
__device__ __align__(16) float g_X2[Bq*Nn*Hh];
__device__ float g_node_vals[Bq*Nn*Aa];
__device__ float g_q[Bq*Nn*Aa];
__device__ __align__(16) float g_msg_forw[Bq*Ee*Aa];
__device__ __align__(16) float g_msg_back[Bq*Ee*Aa];
__device__ float g_qmax[Bq];

// ---------------------------------------------------------
// K0: node MLP + per-node halves of edge layer-1 (X1, X2)
// ---------------------------------------------------------
__global__ void k_node(const float* __restrict__ obs, const float* __restrict__ W1n,
                       const float* __restrict__ b1n, const float* __restrict__ W2n,
                       const float* __restrict__ b2n, const float* __restrict__ W1e) {
    int row0 = blockIdx.x * 8;
    int t = threadIdx.x;
    __shared__ float so[8][64];
    __shared__ float sh[8][128];
    for (int i = t; i < 512; i += 128) so[i >> 6][i & 63] = obs[row0 * 64 + i];
    __syncthreads();
    for (int r = 0; r < 8; r++) {
        float s1 = b1n[t], x1 = 0.f, x2 = 0.f;
#pragma unroll 8
        for (int d = 0; d < 64; d++) {
            float o = so[r][d];
            s1 = fmaf(o, W1n[d * 128 + t], s1);
            x1 = fmaf(o, W1e[d * 128 + t], x1);
            x2 = fmaf(o, W1e[(64 + d) * 128 + t], x2);
        }
        sh[r][t] = fmaxf(s1, 0.f);
        g_X1[(row0 + r) * 128 + t] = x1;
        g_X2[(row0 + r) * 128 + t] = x2;
    }
    __syncthreads();
    if (t < 96) {
        int r = t / 12, a = t - r * 12;
        float nv = b2n[a];
#pragma unroll 8
        for (int k = 0; k < 128; k++) nv = fmaf(sh[r][k], W2n[k * 12 + a], nv);
        g_node_vals[(row0 + r) * 12 + a] = nv;
    }
}

// ---------------------------------------------------------
// K1: edge layer-2 GEMM, f32x2, 64-edge tile -> 2 blocks/SM.
// 384 threads: 8 row-groups (8 rows = 4 pairs) x 48 col-groups (3 cols).
// hT pitch 68; smem = 73.7KB (W) + 34.8KB (hT) = 108.5KB.
// ---------------------------------------------------------
__global__ void __launch_bounds__(384, 2)
k_edge_gemm(const int* __restrict__ ef, const int* __restrict__ et,
            const float* __restrict__ b1e, const float* __restrict__ W2e,
            const float* __restrict__ b2e) {
    extern __shared__ float sm[];
    float* Wsh = sm;                 // 128*144 = 18432 floats
    float* hT  = sm + 18432;         // 128*68  =  8704 floats
    __shared__ int sf[TE], st2[TE];
    int b = blockIdx.y;
    int e0 = blockIdx.x * TE;
    int tid = threadIdx.x;

    if (tid < TE) { sf[tid] = ef[e0 + tid]; st2[tid] = et[e0 + tid]; }
    {
        const float4* W4 = (const float4*)W2e;
        float4* Ws4 = (float4*)Wsh;
        for (int i = tid; i < 4608; i += 384) Ws4[i] = W4[i];
    }
    __syncthreads();

    // hT[k][el] = relu(X1[sf[el]][k] + X2[st[el]][k] + b1e[k]); 8192 elems
    for (int idx = tid; idx < 8192; idx += 384) {
        int el = idx >> 7, k = idx & 127;
        float v = g_X1[(b * Nn + sf[el]) * Hh + k] + g_X2[(b * Nn + st2[el]) * Hh + k] + b1e[k];
        hT[k * 68 + el] = fmaxf(v, 0.f);
    }
    __syncthreads();

    int rg = tid / 48;     // rows rg*8 .. rg*8+7
    int cg = tid % 48;     // cols cg*3 .. cg*3+2

    ull acc[4][3];
#pragma unroll
    for (int j = 0; j < 4; j++)
#pragma unroll
        for (int c = 0; c < 3; c++) acc[j][c] = 0ull;

    const float* hbase = hT + rg * 8;
    const float* wbase = Wsh + cg * 3;

    // 2-stage software pipeline
    ull hv[2][4]; float ws[2][3];
#pragma unroll
    for (int j = 0; j < 4; j++) hv[0][j] = *(const ull*)(hbase + 2 * j);
#pragma unroll
    for (int c = 0; c < 3; c++) ws[0][c] = wbase[c];

#pragma unroll 8
    for (int k = 0; k < 128; k++) {
        int cur = k & 1, nxt = cur ^ 1;
        if (k < 127) {
#pragma unroll
            for (int j = 0; j < 4; j++) hv[nxt][j] = *(const ull*)(hbase + (k + 1) * 68 + 2 * j);
#pragma unroll
            for (int c = 0; c < 3; c++) ws[nxt][c] = wbase[(k + 1) * 144 + c];
        }
        ull wv[3];
#pragma unroll
        for (int c = 0; c < 3; c++)
            asm("mov.b64 %0, {%1, %1};" : "=l"(wv[c]) : "f"(ws[cur][c]));
#pragma unroll
        for (int j = 0; j < 4; j++)
#pragma unroll
            for (int c = 0; c < 3; c++)
                asm("fma.rn.f32x2 %0, %1, %2, %0;" : "+l"(acc[j][c]) : "l"(hv[cur][j]), "l"(wv[c]));
    }

    float bb[3];
#pragma unroll
    for (int c = 0; c < 3; c++) bb[c] = b2e[cg * 3 + c];

    size_t base = ((size_t)b * Ee + e0) * 144 + cg * 3;
#pragma unroll
    for (int j = 0; j < 4; j++) {
        int row = rg * 8 + 2 * j;
#pragma unroll
        for (int c = 0; c < 3; c++) {
            float lo, hi;
            asm("mov.b64 {%0, %1}, %2;" : "=f"(lo), "=f"(hi) : "l"(acc[j][c]));
            g_edge_vals[base + (size_t)row * 144 + c]       = lo + bb[c];
            g_edge_vals[base + (size_t)(row + 1) * 144 + c] = hi + bb[c];
        }
    }
}

// ---------------------------------------------------------
// K4: message update. 64 edges/block, 768 threads.
// first=1: msg arrays are implicitly zero (never read) -> no zero kernels.
// ---------------------------------------------------------
__global__ void __launch_bounds__(768)
k_msg(const int* __restrict__ ef, const int* __restrict__ et, int first) {
    int b = blockIdx.y;
    int e0 = blockIdx.x * 64;
    int tid = threadIdx.x;
    __shared__ float evs[64 * 144];
    __shared__ float su[768], sv[768], smf[768], smb[768];

    const float4* src = (const float4*)&g_edge_vals[((size_t)b * Ee + e0) * 144];
    float4* dst = (float4*)evs;
    const float invE = 1.f / Ee;
#pragma unroll
    for (int i = 0; i < 3; i++) {
        int idx = tid + i * 768;
        float4 v = src[idx];
        v.x *= invE; v.y *= invE; v.z *= invE; v.w *= invE;
        dst[idx] = v;
    }
    int el = tid / 12, a = tid - el * 12;
    int e = e0 + el;
    int f = ef[e], t = et[e];
    size_t mi = ((size_t)b * Ee + e) * 12 + a;
    if (first) {
        su[tid] = g_q[(b * Nn + f) * 12 + a];
        sv[tid] = g_q[(b * Nn + t) * 12 + a];
    } else {
        su[tid] = g_q[(b * Nn + f) * 12 + a] - g_msg_back[mi];
        sv[tid] = g_q[(b * Nn + t) * 12 + a] - g_msg_forw[mi];
    }
    __syncthreads();

    const float* evb = &evs[el * 144];
    const float* sub = &su[el * 12];
    const float* svb = &sv[el * 12];
    float mf = -3.4e38f, mb = -3.4e38f;
#pragma unroll
    for (int x = 0; x < 12; x++) {
        mf = fmaxf(mf, sub[x] + evb[x * 12 + a]);
        mb = fmaxf(mb, svb[x] + evb[a * 12 + x]);
    }
    smf[tid] = mf; smb[tid] = mb;
    __syncthreads();

    float sfo = 0.f, sba = 0.f;
#pragma unroll
    for (int x = 0; x < 12; x++) { sfo += smf[el * 12 + x]; sba += smb[el * 12 + x]; }
    g_msg_forw[mi] = mf - sfo * (1.f / 12.f);
    g_msg_back[mi] = mb - sba * (1.f / 12.f);
}

// ---------------------------------------------------------
// K5: fused q-update + argmax + eval + running-max + output.
// ---------------------------------------------------------
__global__ void __launch_bounds__(1024)
k_qe(const int* __restrict__ ef, const int* __restrict__ et,
     float* __restrict__ out, int first) {
    int b = blockIdx.x, tid = threadIdx.x;
    int w = tid >> 5, lane = tid & 31;
    __shared__ float snv[768];
    __shared__ int sa[64];
    __shared__ float red[1024];
    __shared__ int flag;
    for (int i = tid; i < 768; i += 1024) snv[i] = g_node_vals[b * 768 + i];
    __syncthreads();

    if (first) {
        if (tid < 768) g_q[b * 768 + tid] = snv[tid] * (1.f / Nn);
        if (tid < 64) {
            float best = -3.4e38f; int ba = 0;
#pragma unroll
            for (int a = 0; a < 12; a++) {
                float v = snv[tid * 12 + a];
                if (v > best) { best = v; ba = a; }
            }
            sa[tid] = ba;
        }
    } else {
#pragma unroll
        for (int nn = 0; nn < 2; nn++) {
            int n = w * 2 + nn;
            float acc[12];
#pragma unroll
            for (int a = 0; a < 12; a++) acc[a] = 0.f;

            size_t mbb = ((size_t)b * Ee + n * 63) * 12;
            for (int m = lane; m < 63; m += 32) {
                const float4* p = (const float4*)&g_msg_back[mbb + m * 12];
                float4 p0 = p[0], p1 = p[1], p2 = p[2];
                acc[0] += p0.x; acc[1] += p0.y; acc[2]  += p0.z; acc[3]  += p0.w;
                acc[4] += p1.x; acc[5] += p1.y; acc[6]  += p1.z; acc[7]  += p1.w;
                acc[8] += p2.x; acc[9] += p2.y; acc[10] += p2.z; acc[11] += p2.w;
            }
            for (int i = lane; i < 64; i += 32) {
                if (i == n) continue;
                int e = i * 63 + n - (n > i ? 1 : 0);
                const float4* p = (const float4*)&g_msg_forw[((size_t)b * Ee + e) * 12];
                float4 p0 = p[0], p1 = p[1], p2 = p[2];
                acc[0] += p0.x; acc[1] += p0.y; acc[2]  += p0.z; acc[3]  += p0.w;
                acc[4] += p1.x; acc[5] += p1.y; acc[6]  += p1.z; acc[7]  += p1.w;
                acc[8] += p2.x; acc[9] += p2.y; acc[10] += p2.z; acc[11] += p2.w;
            }
#pragma unroll
            for (int off = 16; off; off >>= 1)
#pragma unroll
                for (int a = 0; a < 12; a++) acc[a] += __shfl_down_sync(0xffffffffu, acc[a], off);

            if (lane == 0) {
                float best = -3.4e38f; int ba = 0;
#pragma unroll
                for (int a = 0; a < 12; a++) {
                    float qa = snv[n * 12 + a] * (1.f / Nn) + acc[a];
                    g_q[(b * 64 + n) * 12 + a] = qa;
                    if (qa > best) { best = qa; ba = a; }
                }
                sa[n] = ba;
            }
        }
    }
    __syncthreads();

    float s = 0.f;
#pragma unroll
    for (int e = tid; e < Ee; e += 1024)
        s += g_edge_vals[((size_t)b * Ee + e) * 144 + sa[ef[e]] * 12 + sa[et[e]]];
    red[tid] = s; __syncthreads();
    for (int o = 512; o; o >>= 1) { if (tid < o) red[tid] += red[tid + o]; __syncthreads(); }
    float es = red[0];
    __syncthreads();

    red[tid] = (tid < 64) ? snv[tid * 12 + sa[tid]] : 0.f;
    __syncthreads();
    for (int o = 512; o; o >>= 1) { if (tid < o) red[tid] += red[tid + o]; __syncthreads(); }

    if (tid == 0) {
        float qv = red[0] / (float)Nn + es / (float)Ee;
        int up = first || (qv > g_qmax[b]);
        if (up) g_qmax[b] = qv;
        out[b] = g_qmax[b];
        flag = up;
    }
    __syncthreads();
    if (flag && tid < 64) out[Bq + b * 64 + tid] = (float)sa[tid];
}

// ---------------------------------------------------------
extern "C" void kernel_launch(void* const* d_in, const int* in_sizes, int n_in,
                              void* d_out, int out_size) {
    const float* obs = (const float*)d_in[0];
    const float* W1n = (const float*)d_in[1];
    const float* b1n = (const float*)d_in[2];
    const float* W2n = (const float*)d_in[3];
    const float* b2n = (const float*)d_in[4];
    const float* W1e = (const float*)d_in[5];
    const float* b1e = (const float*)d_in[6];
    const float* W2e = (const float*)d_in[7];
    const float* b2e = (const float*)d_in[8];
    const int* ef = (const int*)d_in[9];
    const int* et = (const int*)d_in[10];
    float* out = (float*)d_out;

    const int gemm_smem = (18432 + 128 * 68) * 4;   // 108544 B -> 2 blocks/SM
    cudaFuncSetAttribute(k_edge_gemm, cudaFuncAttributeMaxDynamicSharedMemorySize, gemm_smem);

    k_node<<<Bq * Nn / 8, 128>>>(obs, W1n, b1n, W2n, b2n, W1e);                  // idx 0
    k_edge_gemm<<<dim3(Ee / TE, Bq), 384, gemm_smem>>>(ef, et, b1e, W2e, b2e);   // idx 1
    k_qe<<<Bq, 1024>>>(ef, et, out, 1);                                          // idx 2
    for (int it = 0; it < NITERS; it++) {
        k_msg<<<dim3(Ee / 64, Bq), 768>>>(ef, et, it == 0);                      // first msg = idx 3 (profiled)
        k_qe<<<Bq, 1024>>>(ef, et, out, 0);
    }
}

// round 7
// speedup vs baseline: 1.5853x; 1.1802x over previous
#include <cuda_runtime.h>

#define Bq 128
#define Nn 64
#define Dd 64
#define Aa 12
#define Hh 128
#define Ee 4032
#define NITERS 8
#define TE 64   // edges per gemm block

typedef unsigned long long ull;

// -------- device scratch (no allocations allowed) --------
__device__ __align__(16) float g_edge_vals[74317824];   // B*E*A*A, PRE-SCALED by 1/E
__device__ __align__(16) float g_X1[Bq*Nn*Hh];
__device__ __align__(16) float g_X2[Bq*Nn*Hh];
__device__ float g_node_vals[Bq*Nn*Aa];
__device__ float g_q[Bq*Nn*Aa];
__device__ __align__(16) float g_msg_forw[Bq*Ee*Aa];
__device__ __align__(16) float g_msg_back[Bq*Ee*Aa];
__device__ float g_qmax[Bq];

// ---------------------------------------------------------
// K0: node MLP + per-node halves of edge layer-1 (X1, X2)
// ---------------------------------------------------------
__global__ void k_node(const float* __restrict__ obs, const float* __restrict__ W1n,
                       const float* __restrict__ b1n, const float* __restrict__ W2n,
                       const float* __restrict__ b2n, const float* __restrict__ W1e) {
    int row0 = blockIdx.x * 8;
    int t = threadIdx.x;
    __shared__ float so[8][64];
    __shared__ float sh[8][128];
    for (int i = t; i < 512; i += 128) so[i >> 6][i & 63] = obs[row0 * 64 + i];
    __syncthreads();
    for (int r = 0; r < 8; r++) {
        float s1 = b1n[t], x1 = 0.f, x2 = 0.f;
#pragma unroll 8
        for (int d = 0; d < 64; d++) {
            float o = so[r][d];
            s1 = fmaf(o, W1n[d * 128 + t], s1);
            x1 = fmaf(o, W1e[d * 128 + t], x1);
            x2 = fmaf(o, W1e[(64 + d) * 128 + t], x2);
        }
        sh[r][t] = fmaxf(s1, 0.f);
        g_X1[(row0 + r) * 128 + t] = x1;
        g_X2[(row0 + r) * 128 + t] = x2;
    }
    __syncthreads();
    if (t < 96) {
        int r = t / 12, a = t - r * 12;
        float nv = b2n[a];
#pragma unroll 8
        for (int k = 0; k < 128; k++) nv = fmaf(sh[r][k], W2n[k * 12 + a], nv);
        g_node_vals[(row0 + r) * 12 + a] = nv;
    }
}

// ---------------------------------------------------------
// K1: edge layer-2 GEMM, f32x2, 64-edge tile -> 2 blocks/SM.
// Output pre-scaled by 1/E.
// ---------------------------------------------------------
__global__ void __launch_bounds__(384, 2)
k_edge_gemm(const int* __restrict__ ef, const int* __restrict__ et,
            const float* __restrict__ b1e, const float* __restrict__ W2e,
            const float* __restrict__ b2e) {
    extern __shared__ float sm[];
    float* Wsh = sm;                 // 128*144 floats
    float* hT  = sm + 18432;         // 128*68 floats
    __shared__ int sf[TE], st2[TE];
    int b = blockIdx.y;
    int e0 = blockIdx.x * TE;
    int tid = threadIdx.x;

    if (tid < TE) { sf[tid] = ef[e0 + tid]; st2[tid] = et[e0 + tid]; }
    {
        const float4* W4 = (const float4*)W2e;
        float4* Ws4 = (float4*)Wsh;
        for (int i = tid; i < 4608; i += 384) Ws4[i] = W4[i];
    }
    __syncthreads();

    for (int idx = tid; idx < 8192; idx += 384) {
        int el = idx >> 7, k = idx & 127;
        float v = g_X1[(b * Nn + sf[el]) * Hh + k] + g_X2[(b * Nn + st2[el]) * Hh + k] + b1e[k];
        hT[k * 68 + el] = fmaxf(v, 0.f);
    }
    __syncthreads();

    int rg = tid / 48;
    int cg = tid % 48;

    ull acc[4][3];
#pragma unroll
    for (int j = 0; j < 4; j++)
#pragma unroll
        for (int c = 0; c < 3; c++) acc[j][c] = 0ull;

    const float* hbase = hT + rg * 8;
    const float* wbase = Wsh + cg * 3;

    ull hv[2][4]; float ws[2][3];
#pragma unroll
    for (int j = 0; j < 4; j++) hv[0][j] = *(const ull*)(hbase + 2 * j);
#pragma unroll
    for (int c = 0; c < 3; c++) ws[0][c] = wbase[c];

#pragma unroll 8
    for (int k = 0; k < 128; k++) {
        int cur = k & 1, nxt = cur ^ 1;
        if (k < 127) {
#pragma unroll
            for (int j = 0; j < 4; j++) hv[nxt][j] = *(const ull*)(hbase + (k + 1) * 68 + 2 * j);
#pragma unroll
            for (int c = 0; c < 3; c++) ws[nxt][c] = wbase[(k + 1) * 144 + c];
        }
        ull wv[3];
#pragma unroll
        for (int c = 0; c < 3; c++)
            asm("mov.b64 %0, {%1, %1};" : "=l"(wv[c]) : "f"(ws[cur][c]));
#pragma unroll
        for (int j = 0; j < 4; j++)
#pragma unroll
            for (int c = 0; c < 3; c++)
                asm("fma.rn.f32x2 %0, %1, %2, %0;" : "+l"(acc[j][c]) : "l"(hv[cur][j]), "l"(wv[c]));
    }

    float bb[3];
#pragma unroll
    for (int c = 0; c < 3; c++) bb[c] = b2e[cg * 3 + c];
    const float invE = 1.f / Ee;

    size_t base = ((size_t)b * Ee + e0) * 144 + cg * 3;
#pragma unroll
    for (int j = 0; j < 4; j++) {
        int row = rg * 8 + 2 * j;
#pragma unroll
        for (int c = 0; c < 3; c++) {
            float lo, hi;
            asm("mov.b64 {%0, %1}, %2;" : "=f"(lo), "=f"(hi) : "l"(acc[j][c]));
            g_edge_vals[base + (size_t)row * 144 + c]       = (lo + bb[c]) * invE;
            g_edge_vals[base + (size_t)(row + 1) * 144 + c] = (hi + bb[c]) * invE;
        }
    }
}

// ---------------------------------------------------------
// K4: message update, register/shuffle version.
// 512 threads = 32 edges x 16 lanes (12 active). Lane a holds row a
// of the edge's 12x12 matrix in registers; column access via a single
// smem transpose; sums via shfl-xor butterfly. No block barriers.
// sev padded: inactive lanes (sub 12..15) read up to index
// 31*144 + 15 + 132 = 4611, so pad past 4608 (values discarded).
// ---------------------------------------------------------
__global__ void __launch_bounds__(512)
k_msg(const int* __restrict__ ef, const int* __restrict__ et, int first) {
    __shared__ float sev[32 * 144 + 160];
    int b = blockIdx.y;
    int tid = threadIdx.x;
    int elb = tid >> 4;                 // 0..31 edge-in-block
    int sub = tid & 15;                 // lane in group
    int e = blockIdx.x * 32 + elb;
    unsigned g = (tid & 31) & ~15u;     // group base within warp

    size_t evbase = ((size_t)b * Ee + e) * 144;
    size_t mi = ((size_t)b * Ee + e) * 12 + sub;
    float r[12];
    float su = 0.f, sv = 0.f;
    if (sub < 12) {
        float4 r0 = *(const float4*)&g_edge_vals[evbase + sub * 12];
        float4 r1 = *(const float4*)&g_edge_vals[evbase + sub * 12 + 4];
        float4 r2 = *(const float4*)&g_edge_vals[evbase + sub * 12 + 8];
        r[0]=r0.x; r[1]=r0.y; r[2]=r0.z; r[3]=r0.w;
        r[4]=r1.x; r[5]=r1.y; r[6]=r1.z; r[7]=r1.w;
        r[8]=r2.x; r[9]=r2.y; r[10]=r2.z; r[11]=r2.w;
        int f = ef[e], t = et[e];
        su = g_q[(b * Nn + f) * 12 + sub];
        sv = g_q[(b * Nn + t) * 12 + sub];
        if (!first) { su -= g_msg_back[mi]; sv -= g_msg_forw[mi]; }
        float4* sp = (float4*)&sev[elb * 144 + sub * 12];
        sp[0] = r0; sp[1] = r1; sp[2] = r2;
    } else {
#pragma unroll
        for (int x = 0; x < 12; x++) r[x] = 0.f;
    }
    __syncwarp();

    float mf = -3.4e38f, mb = -3.4e38f;
    const float* colp = &sev[elb * 144 + sub];
#pragma unroll
    for (int x = 0; x < 12; x++) {
        float sux = __shfl_sync(0xffffffffu, su, g + x);
        float svx = __shfl_sync(0xffffffffu, sv, g + x);
        mb = fmaxf(mb, svx + r[x]);
        mf = fmaxf(mf, sux + colp[x * 12]);   // sub>=12 lanes read pad area
    }
    float sf = (sub < 12) ? mf : 0.f;
    float sb = (sub < 12) ? mb : 0.f;
#pragma unroll
    for (int o = 8; o; o >>= 1) {
        sf += __shfl_xor_sync(0xffffffffu, sf, o);
        sb += __shfl_xor_sync(0xffffffffu, sb, o);
    }
    if (sub < 12) {
        g_msg_forw[mi] = mf - sf * (1.f / 12.f);
        g_msg_back[mi] = mb - sb * (1.f / 12.f);
    }
}

// ---------------------------------------------------------
// K5: fused q-update + argmax + eval + running-max + output.
// (eval sum uses pre-scaled edge_vals: no final /E)
// ---------------------------------------------------------
__global__ void __launch_bounds__(1024)
k_qe(const int* __restrict__ ef, const int* __restrict__ et,
     float* __restrict__ out, int first) {
    int b = blockIdx.x, tid = threadIdx.x;
    int w = tid >> 5, lane = tid & 31;
    __shared__ float snv[768];
    __shared__ int sa[64];
    __shared__ float red[1024];
    __shared__ int flag;
    for (int i = tid; i < 768; i += 1024) snv[i] = g_node_vals[b * 768 + i];
    __syncthreads();

    if (first) {
        if (tid < 768) g_q[b * 768 + tid] = snv[tid] * (1.f / Nn);
        if (tid < 64) {
            float best = -3.4e38f; int ba = 0;
#pragma unroll
            for (int a = 0; a < 12; a++) {
                float v = snv[tid * 12 + a];
                if (v > best) { best = v; ba = a; }
            }
            sa[tid] = ba;
        }
    } else {
#pragma unroll
        for (int nn = 0; nn < 2; nn++) {
            int n = w * 2 + nn;
            float acc[12];
#pragma unroll
            for (int a = 0; a < 12; a++) acc[a] = 0.f;

            size_t mbb = ((size_t)b * Ee + n * 63) * 12;
            for (int m = lane; m < 63; m += 32) {
                const float4* p = (const float4*)&g_msg_back[mbb + m * 12];
                float4 p0 = p[0], p1 = p[1], p2 = p[2];
                acc[0] += p0.x; acc[1] += p0.y; acc[2]  += p0.z; acc[3]  += p0.w;
                acc[4] += p1.x; acc[5] += p1.y; acc[6]  += p1.z; acc[7]  += p1.w;
                acc[8] += p2.x; acc[9] += p2.y; acc[10] += p2.z; acc[11] += p2.w;
            }
            for (int i = lane; i < 64; i += 32) {
                if (i == n) continue;
                int e = i * 63 + n - (n > i ? 1 : 0);
                const float4* p = (const float4*)&g_msg_forw[((size_t)b * Ee + e) * 12];
                float4 p0 = p[0], p1 = p[1], p2 = p[2];
                acc[0] += p0.x; acc[1] += p0.y; acc[2]  += p0.z; acc[3]  += p0.w;
                acc[4] += p1.x; acc[5] += p1.y; acc[6]  += p1.z; acc[7]  += p1.w;
                acc[8] += p2.x; acc[9] += p2.y; acc[10] += p2.z; acc[11] += p2.w;
            }
#pragma unroll
            for (int off = 16; off; off >>= 1)
#pragma unroll
                for (int a = 0; a < 12; a++) acc[a] += __shfl_down_sync(0xffffffffu, acc[a], off);

            if (lane == 0) {
                float best = -3.4e38f; int ba = 0;
#pragma unroll
                for (int a = 0; a < 12; a++) {
                    float qa = snv[n * 12 + a] * (1.f / Nn) + acc[a];
                    g_q[(b * 64 + n) * 12 + a] = qa;
                    if (qa > best) { best = qa; ba = a; }
                }
                sa[n] = ba;
            }
        }
    }
    __syncthreads();

    float s = 0.f;
#pragma unroll
    for (int e = tid; e < Ee; e += 1024)
        s += g_edge_vals[((size_t)b * Ee + e) * 144 + sa[ef[e]] * 12 + sa[et[e]]];
    red[tid] = s; __syncthreads();
    for (int o = 512; o; o >>= 1) { if (tid < o) red[tid] += red[tid + o]; __syncthreads(); }
    float es = red[0];
    __syncthreads();

    red[tid] = (tid < 64) ? snv[tid * 12 + sa[tid]] : 0.f;
    __syncthreads();
    for (int o = 512; o; o >>= 1) { if (tid < o) red[tid] += red[tid + o]; __syncthreads(); }

    if (tid == 0) {
        float qv = red[0] / (float)Nn + es;   // es pre-scaled by 1/E
        int up = first || (qv > g_qmax[b]);
        if (up) g_qmax[b] = qv;
        out[b] = g_qmax[b];
        flag = up;
    }
    __syncthreads();
    if (flag && tid < 64) out[Bq + b * 64 + tid] = (float)sa[tid];
}

// ---------------------------------------------------------
extern "C" void kernel_launch(void* const* d_in, const int* in_sizes, int n_in,
                              void* d_out, int out_size) {
    const float* obs = (const float*)d_in[0];
    const float* W1n = (const float*)d_in[1];
    const float* b1n = (const float*)d_in[2];
    const float* W2n = (const float*)d_in[3];
    const float* b2n = (const float*)d_in[4];
    const float* W1e = (const float*)d_in[5];
    const float* b1e = (const float*)d_in[6];
    const float* W2e = (const float*)d_in[7];
    const float* b2e = (const float*)d_in[8];
    const int* ef = (const int*)d_in[9];
    const int* et = (const int*)d_in[10];
    float* out = (float*)d_out;

    const int gemm_smem = (18432 + 128 * 68) * 4;   // 108544 B -> 2 blocks/SM
    cudaFuncSetAttribute(k_edge_gemm, cudaFuncAttributeMaxDynamicSharedMemorySize, gemm_smem);

    k_node<<<Bq * Nn / 8, 128>>>(obs, W1n, b1n, W2n, b2n, W1e);                  // idx 0
    k_edge_gemm<<<dim3(Ee / TE, Bq), 384, gemm_smem>>>(ef, et, b1e, W2e, b2e);   // idx 1
    k_qe<<<Bq, 1024>>>(ef, et, out, 1);                                          // idx 2
    for (int it = 0; it < NITERS; it++) {
        k_msg<<<dim3(Ee / 32, Bq), 512>>>(ef, et, it == 0);                      // idx 3,5,... (5 profiled)
        k_qe<<<Bq, 1024>>>(ef, et, out, 0);
    }
}